// round 14
// baseline (speedup 1.0000x reference)
#include <cuda_runtime.h>
#include <cuda_fp16.h>
#include <math.h>
#include <stdint.h>

#define D_MODEL 1024
#define N_HEADS 16
#define HEAD_DIM 64
#define D_FF     4096
#define BATCH    2
#define SEQ      2048
#define M_TOK    (BATCH*SEQ)   /* 4096 token rows */

// ---------------- scratch (static device globals; no allocation) -------------
__device__ __half g_h1 [M_TOK*D_MODEL];
__device__ __half g_qkv[3*M_TOK*D_MODEL];
__device__ __half g_ctx[M_TOK*D_MODEL];
__device__ __half g_h2 [M_TOK*D_MODEL];
__device__ __half g_ff [M_TOK*D_FF];
__device__ float  g_x1 [M_TOK*D_MODEL];
__device__ __half g_wh [12*1024*1024];   // fp16 weights: q,k,v,o,fc1,fc2

// ---------------- helpers -----------------------------------------------------
__device__ __forceinline__ void mma_f16(float* d, const uint32_t* a, const uint32_t* b) {
    asm volatile(
        "mma.sync.aligned.m16n8k16.row.col.f32.f16.f16.f32 "
        "{%0,%1,%2,%3}, {%4,%5,%6,%7}, {%8,%9}, {%0,%1,%2,%3};"
        : "+f"(d[0]), "+f"(d[1]), "+f"(d[2]), "+f"(d[3])
        : "r"(a[0]), "r"(a[1]), "r"(a[2]), "r"(a[3]), "r"(b[0]), "r"(b[1]));
}
__device__ __forceinline__ void ldsm_x4(uint32_t* r, uint32_t addr) {
    asm volatile("ldmatrix.sync.aligned.m8n8.x4.shared.b16 {%0,%1,%2,%3}, [%4];"
                 : "=r"(r[0]), "=r"(r[1]), "=r"(r[2]), "=r"(r[3]) : "r"(addr));
}
__device__ __forceinline__ void ldsm_x4_t(uint32_t* r, uint32_t addr) {
    asm volatile("ldmatrix.sync.aligned.m8n8.x4.trans.shared.b16 {%0,%1,%2,%3}, [%4];"
                 : "=r"(r[0]), "=r"(r[1]), "=r"(r[2]), "=r"(r[3]) : "r"(addr));
}
__device__ __forceinline__ uint32_t smem_u32(const void* p) {
    uint32_t a;
    asm("{ .reg .u64 t; cvta.to.shared.u64 t, %1; cvt.u32.u64 %0, t; }" : "=r"(a) : "l"(p));
    return a;
}
__device__ __forceinline__ uint32_t packh2(float x, float y) {
    half2 h = __floats2half2_rn(x, y);
    return *(uint32_t*)&h;
}

// ---------------- LayerNorm: warp-per-row, shuffle-only ------------------------
__global__ void __launch_bounds__(256)
ln_kernel(const float* __restrict__ x,
          const float* __restrict__ gamma,
          const float* __restrict__ beta,
          __half* __restrict__ out) {
    const int wid = threadIdx.x >> 5, lane = threadIdx.x & 31;
    const int row = blockIdx.x * 8 + wid;
    const float4* xr = (const float4*)(x + (size_t)row * D_MODEL);
    float4 v[8];
    float s = 0.0f;
    #pragma unroll
    for (int i = 0; i < 8; i++) {
        v[i] = xr[i * 32 + lane];
        s += v[i].x + v[i].y + v[i].z + v[i].w;
    }
    #pragma unroll
    for (int o = 16; o > 0; o >>= 1) s += __shfl_xor_sync(0xFFFFFFFFu, s, o);
    const float mean = s * (1.0f / D_MODEL);
    float s2 = 0.0f;
    #pragma unroll
    for (int i = 0; i < 8; i++) {
        float a = v[i].x - mean, b = v[i].y - mean, c = v[i].z - mean, d = v[i].w - mean;
        s2 += a * a + b * b + c * c + d * d;
    }
    #pragma unroll
    for (int o = 16; o > 0; o >>= 1) s2 += __shfl_xor_sync(0xFFFFFFFFu, s2, o);
    const float rstd = rsqrtf(s2 * (1.0f / D_MODEL) + 1e-5f);
    __half* orow = out + (size_t)row * D_MODEL;
    #pragma unroll
    for (int i = 0; i < 8; i++) {
        const float4 gg = ((const float4*)gamma)[i * 32 + lane];
        const float4 bb = ((const float4*)beta)[i * 32 + lane];
        uint2 o2;
        o2.x = packh2((v[i].x - mean) * rstd * gg.x + bb.x,
                      (v[i].y - mean) * rstd * gg.y + bb.y);
        o2.y = packh2((v[i].z - mean) * rstd * gg.z + bb.z,
                      (v[i].w - mean) * rstd * gg.w + bb.w);
        *(uint2*)(orow + i * 128 + lane * 4) = o2;
    }
}

// ---------------- all-weights -> fp16 conversion (one launch) -----------------
__global__ void tohalf_all(const float* __restrict__ w0, const float* __restrict__ w1,
                           const float* __restrict__ w2, const float* __restrict__ w3,
                           const float* __restrict__ w4, const float* __restrict__ w5,
                           __half* __restrict__ out) {
    const int Q4 = 256 * 1024;           // 1M floats in float4 units
    int i = blockIdx.x * blockDim.x + threadIdx.x;   // float4 index, [0, 3M)
    const float* src; int base;
    if      (i <     Q4) { src = w0; base = 0;      }
    else if (i < 2 * Q4) { src = w1; base = Q4;     }
    else if (i < 3 * Q4) { src = w2; base = 2 * Q4; }
    else if (i < 4 * Q4) { src = w3; base = 3 * Q4; }
    else if (i < 8 * Q4) { src = w4; base = 4 * Q4; }
    else                 { src = w5; base = 8 * Q4; }
    float4 v = ((const float4*)src)[i - base];
    ((half2*)out)[i * 2]     = __floats2half2_rn(v.x, v.y);
    ((half2*)out)[i * 2 + 1] = __floats2half2_rn(v.z, v.w);
}

// ---------------- FP16 mma.sync GEMM:  C[M,N] = A[M,K] @ W[N,K]^T -------------
// 128x128 CTA tile, BK=64, 128 threads (4 warps, 2x2 grid, 64x64 warp tiles),
// ldmatrix fragments, 3-stage cp.async pipeline (16 barriers for K=1024),
// fp32 accumulators, 2 CTAs/SM.  Row stride 72 halves (144B) -> conflict-free.
#define GROW    72
#define STG_H   (128*GROW)
#define STAGE_H (2*STG_H)
#define NSTAGE  3
#define GEMM_SMEM_BYTES (NSTAGE*STAGE_H*2 + 512)

__device__ __forceinline__ void load_chunk_h(
    __half* smem_h, const __half* __restrict__ A, const __half* __restrict__ W,
    int bm, int bn, int K, int c, int tid) {
    __half* stage = smem_h + (c % NSTAGE) * STAGE_H;
    #pragma unroll
    for (int it = 0; it < 16; it++) {
        int i = tid + it * 128;          // 0..2047
        bool isA = i < 1024;
        int j = i & 1023;
        int row = j >> 3, seg = j & 7;   // row 0..127, 16B seg 0..7 (64 halves)
        __half* dst = stage + (isA ? 0 : STG_H) + row * GROW + seg * 8;
        const __half* src = (isA ? A + (size_t)(bm + row) * K
                                 : W + (size_t)(bn + row) * K) + c * 64 + seg * 8;
        asm volatile("cp.async.cg.shared.global [%0], [%1], 16;"
                     :: "r"(smem_u32(dst)), "l"(src));
    }
    asm volatile("cp.async.commit_group;" ::: "memory");
}

template<int EPI>
__global__ void __launch_bounds__(128, 2)
mma_gemm(const __half* __restrict__ A, const __half* __restrict__ W,
         const float* __restrict__ b0, const float* __restrict__ b1,
         const float* __restrict__ b2, const float* __restrict__ res,
         void* __restrict__ Cv, int M, int N, int K) {
    extern __shared__ char smem[];
    __half* smem_h = (__half*)smem;
    float*  sbias  = (float*)(smem + NSTAGE * STAGE_H * 2);

    const int tid  = threadIdx.x;
    const int wid  = tid >> 5, lane = tid & 31;
    const int wm   = wid >> 1, wn = wid & 1;        // 2 x 2 warp grid, 64x64 tiles
    const int bm   = blockIdx.y * 128, bn = blockIdx.x * 128;
    const int NC   = K >> 6;                         // BK=64 chunks

    const float* bsel = b0;
    int bcol = bn;
    if (EPI == 3) {
        const int which = bn >> 10;
        bsel = (which == 0) ? b0 : (which == 1) ? b1 : b2;
        bcol = bn & 1023;
    }
    sbias[tid] = bsel[bcol + tid];

    float acc[4][8][4];
    #pragma unroll
    for (int mt = 0; mt < 4; mt++)
        #pragma unroll
        for (int nt = 0; nt < 8; nt++)
            #pragma unroll
            for (int e = 0; e < 4; e++) acc[mt][nt][e] = 0.0f;

    load_chunk_h(smem_h, A, W, bm, bn, K, 0, tid);
    load_chunk_h(smem_h, A, W, bm, bn, K, 1, tid);

    const int g = lane >> 3, r8 = lane & 7;
    const uint32_t sb = smem_u32(smem_h);
    const uint32_t aBase = sb + ((wm * 64 + (g & 1) * 8 + r8) * GROW + (g >> 1) * 8) * 2;
    const uint32_t bBase = sb + (STG_H + (wn * 64 + (g >> 1) * 8 + r8) * GROW + (g & 1) * 8) * 2;

    for (int c = 0; c < NC; c++) {
        const int rem = NC - 1 - c;
        if (rem >= 1)      asm volatile("cp.async.wait_group 1;" ::: "memory");
        else               asm volatile("cp.async.wait_group 0;" ::: "memory");
        __syncthreads();   // chunk c ready; all warps done with chunk c-1

        if (c + 2 < NC) load_chunk_h(smem_h, A, W, bm, bn, K, c + 2, tid);

        const uint32_t stOff = (uint32_t)(c % NSTAGE) * (STAGE_H * 2);
        #pragma unroll
        for (int ks = 0; ks < 4; ks++) {            // 4 x k16 within BK=64
            uint32_t a[4][4], b[4][4];
            #pragma unroll
            for (int mt = 0; mt < 4; mt++)
                ldsm_x4(a[mt], aBase + stOff + mt * (16 * GROW * 2) + ks * 32);
            #pragma unroll
            for (int j = 0; j < 4; j++)
                ldsm_x4(b[j], bBase + stOff + j * (16 * GROW * 2) + ks * 32);
            #pragma unroll
            for (int mt = 0; mt < 4; mt++)
                #pragma unroll
                for (int j = 0; j < 4; j++) {
                    mma_f16(acc[mt][2 * j],     a[mt], b[j]);
                    mma_f16(acc[mt][2 * j + 1], a[mt], b[j] + 2);
                }
        }
    }

    const int lr4 = lane >> 2, lc = lane & 3;
    const int cstride = (EPI == 3) ? 1024 : N;
    __half* Ch = (__half*)Cv;
    if (EPI == 3) Ch += (size_t)(bn >> 10) * M_TOK * 1024;
    const int cbn = (EPI == 3) ? (bn & 1023) : bn;

    #pragma unroll
    for (int mt = 0; mt < 4; mt++) {
        const int row0 = bm + wm * 64 + mt * 16 + lr4;
        #pragma unroll
        for (int nt = 0; nt < 8; nt++) {
            const int coll = wn * 64 + nt * 8 + lc * 2;
            const int col  = cbn + coll;
            #pragma unroll
            for (int half_i = 0; half_i < 2; half_i++) {
                const int row = row0 + half_i * 8;
                float ox = acc[mt][nt][half_i * 2 + 0] + sbias[coll];
                float oy = acc[mt][nt][half_i * 2 + 1] + sbias[coll + 1];
                if (EPI == 0 || EPI == 3) {
                    *(half2*)(Ch + (size_t)row * cstride + col) = __floats2half2_rn(ox, oy);
                } else if (EPI == 1) {
                    ox = 0.5f * ox * (1.0f + erff(ox * 0.70710678118654752f));
                    oy = 0.5f * oy * (1.0f + erff(oy * 0.70710678118654752f));
                    *(half2*)(Ch + (size_t)row * cstride + col) = __floats2half2_rn(ox, oy);
                } else {
                    const float2 rv = *(const float2*)(res + (size_t)row * N + col);
                    float2 o; o.x = ox + rv.x; o.y = oy + rv.y;
                    *(float2*)((float*)Cv + (size_t)row * N + col) = o;
                }
            }
        }
    }
}

// ---------------- Tensor-core causal flash attention (fp16, FA2-style) --------
// exp2-domain softmax: Q pre-scaled by 0.125*log2(e); exp via exp2f.
#define ATS 72
#define AT_TILE (64*ATS)
#define AT_SMEM ((128*ATS + 4*AT_TILE)*2)

__device__ __forceinline__ void at_prefetch(
    __half* Ks, __half* Vs, const __half* __restrict__ K, const __half* __restrict__ V,
    size_t kbase, int st, int tid) {
    __half* kd = Ks + st * AT_TILE;
    __half* vd = Vs + st * AT_TILE;
    #pragma unroll
    for (int it = 0; it < 2; it++) {
        const int i = tid + it * 256;      // 0..511
        const int row = i >> 3, seg = i & 7;
        const size_t go = kbase + (size_t)row * D_MODEL + seg * 8;
        asm volatile("cp.async.cg.shared.global [%0], [%1], 16;"
                     :: "r"(smem_u32(kd + row * ATS + seg * 8)), "l"(K + go));
        asm volatile("cp.async.cg.shared.global [%0], [%1], 16;"
                     :: "r"(smem_u32(vd + row * ATS + seg * 8)), "l"(V + go));
    }
    asm volatile("cp.async.commit_group;" ::: "memory");
}

__global__ void __launch_bounds__(256, 2)
attn_tc(const __half* __restrict__ Q, const __half* __restrict__ K,
        const __half* __restrict__ V, __half* __restrict__ O) {
    extern __shared__ __half smh[];
    __half* Qs = smh;                      // [128][72]
    __half* Ks = Qs + 128 * ATS;           // 2 x [64][72]
    __half* Vs = Ks + 2 * AT_TILE;         // 2 x [64][72] (raw [tok][d])
    const int tid = threadIdx.x;
    const int wid = tid >> 5, lane = tid & 31;
    const int g = lane >> 3, r8 = lane & 7;
    const int lr4 = lane >> 2, lc = lane & 3;

    const int qb = (gridDim.x - 1) - blockIdx.x;   // heavy tiles first
    const int h = blockIdx.y, b = blockIdx.z;
    const size_t qbase = ((size_t)(b * SEQ + qb * 128) * D_MODEL) + h * HEAD_DIM;
    const size_t kvbase0 = ((size_t)(b * SEQ) * D_MODEL) + h * HEAD_DIM;

    at_prefetch(Ks, Vs, K, V, kvbase0, 0, tid);

    // Q scale folds softmax 1/sqrt(dh) AND log2(e): 0.125 * 1.4426950408889634
    const half2 scl = __half2half2(__float2half(0.18033687919464111f));
    #pragma unroll
    for (int it = 0; it < 4; it++) {
        const int i = tid + it * 256;
        const int row = i >> 3, seg = i & 7;
        const half2* src = (const half2*)(Q + qbase + (size_t)row * D_MODEL + seg * 8);
        half2* dst = (half2*)(Qs + row * ATS + seg * 8);
        #pragma unroll
        for (int j = 0; j < 4; j++) dst[j] = __hmul2(src[j], scl);
    }

    float m[2], l[2], acc[8][4];
    m[0] = m[1] = -1e30f; l[0] = l[1] = 0.0f;
    #pragma unroll
    for (int nt = 0; nt < 8; nt++)
        #pragma unroll
        for (int e = 0; e < 4; e++) acc[nt][e] = 0.0f;

    const uint32_t qA = smem_u32(Qs) + ((wid * 16 + (g & 1) * 8 + r8) * ATS + (g >> 1) * 8) * 2;
    const uint32_t kB0 = smem_u32(Ks) + (((g >> 1) * 8 + r8) * ATS + (g & 1) * 8) * 2;
    const uint32_t vB0 = smem_u32(Vs) + (((g & 1) * 8 + r8) * ATS + (g >> 1) * 8) * 2;

    const int ntk = 2 * qb + 2;
    for (int kt = 0; kt < ntk; kt++) {
        if (kt + 1 < ntk)
            at_prefetch(Ks, Vs, K, V, kvbase0 + (size_t)(kt + 1) * 64 * D_MODEL, (kt + 1) & 1, tid);
        if (kt + 1 < ntk) asm volatile("cp.async.wait_group 1;" ::: "memory");
        else              asm volatile("cp.async.wait_group 0;" ::: "memory");
        __syncthreads();

        const uint32_t stB = (uint32_t)(kt & 1) * (AT_TILE * 2);
        const uint32_t kB = kB0 + stB, vB = vB0 + stB;

        float s[8][4];
        #pragma unroll
        for (int nt = 0; nt < 8; nt++)
            #pragma unroll
            for (int e = 0; e < 4; e++) s[nt][e] = 0.0f;

        #pragma unroll
        for (int ks = 0; ks < 4; ks++) {
            uint32_t aQ[4];
            ldsm_x4(aQ, qA + ks * 32);
            #pragma unroll
            for (int j = 0; j < 4; j++) {
                uint32_t bb[4];
                ldsm_x4(bb, kB + j * (16 * ATS * 2) + ks * 32);
                mma_f16(s[2 * j],     aQ, bb);
                mma_f16(s[2 * j + 1], aQ, bb + 2);
            }
        }

        if (kt >= 2 * qb) {
            const int row0 = qb * 128 + wid * 16 + lr4;
            #pragma unroll
            for (int nt = 0; nt < 8; nt++) {
                const int col0 = kt * 64 + nt * 8 + 2 * lc;
                if (col0     > row0)     s[nt][0] = -1e9f;
                if (col0 + 1 > row0)     s[nt][1] = -1e9f;
                if (col0     > row0 + 8) s[nt][2] = -1e9f;
                if (col0 + 1 > row0 + 8) s[nt][3] = -1e9f;
            }
        }

        // online softmax in log2 domain (exp2f = single MUFU, no hidden mul)
        #pragma unroll
        for (int hf = 0; hf < 2; hf++) {
            float mx = m[hf];
            #pragma unroll
            for (int nt = 0; nt < 8; nt++)
                mx = fmaxf(mx, fmaxf(s[nt][hf * 2], s[nt][hf * 2 + 1]));
            mx = fmaxf(mx, __shfl_xor_sync(0xFFFFFFFFu, mx, 1));
            mx = fmaxf(mx, __shfl_xor_sync(0xFFFFFFFFu, mx, 2));
            const float corr = exp2f(m[hf] - mx);
            m[hf] = mx;
            float sum = 0.0f;
            #pragma unroll
            for (int nt = 0; nt < 8; nt++) {
                float p0 = exp2f(s[nt][hf * 2]     - mx);
                float p1 = exp2f(s[nt][hf * 2 + 1] - mx);
                s[nt][hf * 2] = p0; s[nt][hf * 2 + 1] = p1;
                sum += p0 + p1;
            }
            sum += __shfl_xor_sync(0xFFFFFFFFu, sum, 1);
            sum += __shfl_xor_sync(0xFFFFFFFFu, sum, 2);
            l[hf] = l[hf] * corr + sum;
            #pragma unroll
            for (int nt = 0; nt < 8; nt++) {
                acc[nt][hf * 2]     *= corr;
                acc[nt][hf * 2 + 1] *= corr;
            }
        }

        #pragma unroll
        for (int ks = 0; ks < 4; ks++) {
            uint32_t aP[4];
            aP[0] = packh2(s[2 * ks][0],     s[2 * ks][1]);
            aP[1] = packh2(s[2 * ks][2],     s[2 * ks][3]);
            aP[2] = packh2(s[2 * ks + 1][0], s[2 * ks + 1][1]);
            aP[3] = packh2(s[2 * ks + 1][2], s[2 * ks + 1][3]);
            #pragma unroll
            for (int j = 0; j < 4; j++) {
                uint32_t bb[4];
                ldsm_x4_t(bb, vB + ks * (16 * ATS * 2) + j * 32);
                mma_f16(acc[2 * j],     aP, bb);
                mma_f16(acc[2 * j + 1], aP, bb + 2);
            }
        }
        __syncthreads();
    }

    const float inv0 = 1.0f / l[0], inv1 = 1.0f / l[1];
    const int row0 = qb * 128 + wid * 16 + lr4;
    #pragma unroll
    for (int nt = 0; nt < 8; nt++) {
        const int col = h * HEAD_DIM + nt * 8 + 2 * lc;
        *(half2*)(O + (size_t)(b * SEQ + row0) * D_MODEL + col) =
            __floats2half2_rn(acc[nt][0] * inv0, acc[nt][1] * inv0);
        *(half2*)(O + (size_t)(b * SEQ + row0 + 8) * D_MODEL + col) =
            __floats2half2_rn(acc[nt][2] * inv1, acc[nt][3] * inv1);
    }
}

// ---------------- launch ------------------------------------------------------
extern "C" void kernel_launch(void* const* d_in, const int* in_sizes, int n_in,
                              void* d_out, int out_size) {
    const float* x     = (const float*)d_in[0];
    const float* wq_w  = (const float*)d_in[2];
    const float* wq_b  = (const float*)d_in[3];
    const float* wk_w  = (const float*)d_in[4];
    const float* wk_b  = (const float*)d_in[5];
    const float* wv_w  = (const float*)d_in[6];
    const float* wv_b  = (const float*)d_in[7];
    const float* wo_w  = (const float*)d_in[8];
    const float* wo_b  = (const float*)d_in[9];
    const float* fc1_w = (const float*)d_in[10];
    const float* fc1_b = (const float*)d_in[11];
    const float* fc2_w = (const float*)d_in[12];
    const float* fc2_b = (const float*)d_in[13];
    const float* ln1_g = (const float*)d_in[14];
    const float* ln1_b = (const float*)d_in[15];
    const float* ln2_g = (const float*)d_in[16];
    const float* ln2_b = (const float*)d_in[17];

    __half *h1, *qkv, *ctx, *h2, *ff, *wh;
    float *x1;
    cudaGetSymbolAddress((void**)&h1,  g_h1);
    cudaGetSymbolAddress((void**)&qkv, g_qkv);
    cudaGetSymbolAddress((void**)&ctx, g_ctx);
    cudaGetSymbolAddress((void**)&h2,  g_h2);
    cudaGetSymbolAddress((void**)&ff,  g_ff);
    cudaGetSymbolAddress((void**)&x1,  g_x1);
    cudaGetSymbolAddress((void**)&wh,  g_wh);

    cudaFuncSetAttribute(mma_gemm<1>, cudaFuncAttributeMaxDynamicSharedMemorySize, GEMM_SMEM_BYTES);
    cudaFuncSetAttribute(mma_gemm<2>, cudaFuncAttributeMaxDynamicSharedMemorySize, GEMM_SMEM_BYTES);
    cudaFuncSetAttribute(mma_gemm<3>, cudaFuncAttributeMaxDynamicSharedMemorySize, GEMM_SMEM_BYTES);
    cudaFuncSetAttribute(attn_tc,     cudaFuncAttributeMaxDynamicSharedMemorySize, AT_SMEM);

    const int MM = 1024 * 1024;
    __half* wh_qkv = wh;
    __half* wh_o   = wh + 3 * MM;
    __half* wh_fc1 = wh + 4 * MM;
    __half* wh_fc2 = wh + 8 * MM;

    tohalf_all<<<12 * MM / 4 / 256, 256>>>(wq_w, wk_w, wv_w, wo_w, fc1_w, fc2_w, wh);

    __half* q = qkv;
    __half* k = qkv + (size_t)M_TOK * D_MODEL;
    __half* v = qkv + 2 * (size_t)M_TOK * D_MODEL;

    // --- attention sub-block (pre-norm) ---
    ln_kernel<<<M_TOK / 8, 256>>>(x, ln1_g, ln1_b, h1);
    mma_gemm<3><<<dim3(24, 32), 128, GEMM_SMEM_BYTES>>>(
        h1, wh_qkv, wq_b, wk_b, wv_b, nullptr, qkv, M_TOK, 3 * D_MODEL, D_MODEL);
    attn_tc<<<dim3(SEQ / 128, N_HEADS, BATCH), 256, AT_SMEM>>>(q, k, v, ctx);
    mma_gemm<2><<<dim3(8, 32), 128, GEMM_SMEM_BYTES>>>(
        ctx, wh_o, wo_b, nullptr, nullptr, x, x1, M_TOK, D_MODEL, D_MODEL);

    // --- FFN sub-block (pre-norm) ---
    ln_kernel<<<M_TOK / 8, 256>>>(x1, ln2_g, ln2_b, h2);
    mma_gemm<1><<<dim3(32, 32), 128, GEMM_SMEM_BYTES>>>(
        h2, wh_fc1, fc1_b, nullptr, nullptr, nullptr, ff, M_TOK, D_FF, D_MODEL);
    mma_gemm<2><<<dim3(8, 32), 128, GEMM_SMEM_BYTES>>>(
        ff, wh_fc2, fc2_b, nullptr, nullptr, x1, d_out, M_TOK, D_MODEL, D_FF);
}

// round 15
// speedup vs baseline: 1.0260x; 1.0260x over previous
#include <cuda_runtime.h>
#include <cuda_fp16.h>
#include <math.h>
#include <stdint.h>

#define D_MODEL 1024
#define N_HEADS 16
#define HEAD_DIM 64
#define D_FF     4096
#define BATCH    2
#define SEQ      2048
#define M_TOK    (BATCH*SEQ)   /* 4096 token rows */

// ---------------- scratch (static device globals; no allocation) -------------
__device__ __half g_h1 [M_TOK*D_MODEL];
__device__ __half g_qkv[3*M_TOK*D_MODEL];
__device__ __half g_ctx[M_TOK*D_MODEL];
__device__ __half g_h2 [M_TOK*D_MODEL];
__device__ __half g_ff [M_TOK*D_FF];
__device__ float  g_x1 [M_TOK*D_MODEL];
__device__ __half g_wh [12*1024*1024];   // fp16 weights: q,k,v,o,fc1,fc2

// ---------------- helpers -----------------------------------------------------
__device__ __forceinline__ void mma_f16(float* d, const uint32_t* a, const uint32_t* b) {
    asm volatile(
        "mma.sync.aligned.m16n8k16.row.col.f32.f16.f16.f32 "
        "{%0,%1,%2,%3}, {%4,%5,%6,%7}, {%8,%9}, {%0,%1,%2,%3};"
        : "+f"(d[0]), "+f"(d[1]), "+f"(d[2]), "+f"(d[3])
        : "r"(a[0]), "r"(a[1]), "r"(a[2]), "r"(a[3]), "r"(b[0]), "r"(b[1]));
}
__device__ __forceinline__ void ldsm_x4(uint32_t* r, uint32_t addr) {
    asm volatile("ldmatrix.sync.aligned.m8n8.x4.shared.b16 {%0,%1,%2,%3}, [%4];"
                 : "=r"(r[0]), "=r"(r[1]), "=r"(r[2]), "=r"(r[3]) : "r"(addr));
}
__device__ __forceinline__ void ldsm_x4_t(uint32_t* r, uint32_t addr) {
    asm volatile("ldmatrix.sync.aligned.m8n8.x4.trans.shared.b16 {%0,%1,%2,%3}, [%4];"
                 : "=r"(r[0]), "=r"(r[1]), "=r"(r[2]), "=r"(r[3]) : "r"(addr));
}
__device__ __forceinline__ uint32_t smem_u32(const void* p) {
    uint32_t a;
    asm("{ .reg .u64 t; cvta.to.shared.u64 t, %1; cvt.u32.u64 %0, t; }" : "=r"(a) : "l"(p));
    return a;
}
__device__ __forceinline__ uint32_t packh2(float x, float y) {
    half2 h = __floats2half2_rn(x, y);
    return *(uint32_t*)&h;
}
__device__ __forceinline__ uint32_t h2exp2(uint32_t x) {
    uint32_t r;
    asm("ex2.approx.f16x2 %0, %1;" : "=r"(r) : "r"(x));
    return r;
}

// ---------------- LayerNorm: warp-per-row, shuffle-only ------------------------
__global__ void __launch_bounds__(256)
ln_kernel(const float* __restrict__ x,
          const float* __restrict__ gamma,
          const float* __restrict__ beta,
          __half* __restrict__ out) {
    const int wid = threadIdx.x >> 5, lane = threadIdx.x & 31;
    const int row = blockIdx.x * 8 + wid;
    const float4* xr = (const float4*)(x + (size_t)row * D_MODEL);
    float4 v[8];
    float s = 0.0f;
    #pragma unroll
    for (int i = 0; i < 8; i++) {
        v[i] = xr[i * 32 + lane];
        s += v[i].x + v[i].y + v[i].z + v[i].w;
    }
    #pragma unroll
    for (int o = 16; o > 0; o >>= 1) s += __shfl_xor_sync(0xFFFFFFFFu, s, o);
    const float mean = s * (1.0f / D_MODEL);
    float s2 = 0.0f;
    #pragma unroll
    for (int i = 0; i < 8; i++) {
        float a = v[i].x - mean, b = v[i].y - mean, c = v[i].z - mean, d = v[i].w - mean;
        s2 += a * a + b * b + c * c + d * d;
    }
    #pragma unroll
    for (int o = 16; o > 0; o >>= 1) s2 += __shfl_xor_sync(0xFFFFFFFFu, s2, o);
    const float rstd = rsqrtf(s2 * (1.0f / D_MODEL) + 1e-5f);
    __half* orow = out + (size_t)row * D_MODEL;
    #pragma unroll
    for (int i = 0; i < 8; i++) {
        const float4 gg = ((const float4*)gamma)[i * 32 + lane];
        const float4 bb = ((const float4*)beta)[i * 32 + lane];
        uint2 o2;
        o2.x = packh2((v[i].x - mean) * rstd * gg.x + bb.x,
                      (v[i].y - mean) * rstd * gg.y + bb.y);
        o2.y = packh2((v[i].z - mean) * rstd * gg.z + bb.z,
                      (v[i].w - mean) * rstd * gg.w + bb.w);
        *(uint2*)(orow + i * 128 + lane * 4) = o2;
    }
}

// ---------------- all-weights -> fp16 conversion (one launch) -----------------
__global__ void tohalf_all(const float* __restrict__ w0, const float* __restrict__ w1,
                           const float* __restrict__ w2, const float* __restrict__ w3,
                           const float* __restrict__ w4, const float* __restrict__ w5,
                           __half* __restrict__ out) {
    const int Q4 = 256 * 1024;           // 1M floats in float4 units
    int i = blockIdx.x * blockDim.x + threadIdx.x;   // float4 index, [0, 3M)
    const float* src; int base;
    if      (i <     Q4) { src = w0; base = 0;      }
    else if (i < 2 * Q4) { src = w1; base = Q4;     }
    else if (i < 3 * Q4) { src = w2; base = 2 * Q4; }
    else if (i < 4 * Q4) { src = w3; base = 3 * Q4; }
    else if (i < 8 * Q4) { src = w4; base = 4 * Q4; }
    else                 { src = w5; base = 8 * Q4; }
    float4 v = ((const float4*)src)[i - base];
    ((half2*)out)[i * 2]     = __floats2half2_rn(v.x, v.y);
    ((half2*)out)[i * 2 + 1] = __floats2half2_rn(v.z, v.w);
}

// ---------------- FP16 mma.sync GEMM:  C[M,N] = A[M,K] @ W[N,K]^T -------------
// 128x128 CTA tile, BK=32, 128 threads (4 warps, 2x2 grid, 64x64 warp tiles),
// ldmatrix fragments, 4-stage cp.async pipeline, fp32 accumulators, 2 CTAs/SM.
// (R13 proven config)
#define STG_H   (128*40)
#define STAGE_H (2*STG_H)
#define NSTAGE  4
#define GEMM_SMEM_BYTES (NSTAGE*STAGE_H*2 + 512)

__device__ __forceinline__ void load_chunk_h(
    __half* smem_h, const __half* __restrict__ A, const __half* __restrict__ W,
    int bm, int bn, int K, int c, int tid) {
    __half* stage = smem_h + (c & (NSTAGE - 1)) * STAGE_H;
    #pragma unroll
    for (int it = 0; it < 8; it++) {
        int i = tid + it * 128;          // 0..1023
        bool isA = i < 512;
        int j = i & 511;
        int row = j >> 2, seg = j & 3;   // row 0..127, 16B seg 0..3
        __half* dst = stage + (isA ? 0 : STG_H) + row * 40 + seg * 8;
        const __half* src = (isA ? A + (size_t)(bm + row) * K
                                 : W + (size_t)(bn + row) * K) + c * 32 + seg * 8;
        asm volatile("cp.async.cg.shared.global [%0], [%1], 16;"
                     :: "r"(smem_u32(dst)), "l"(src));
    }
    asm volatile("cp.async.commit_group;" ::: "memory");
}

template<int EPI>
__global__ void __launch_bounds__(128, 2)
mma_gemm(const __half* __restrict__ A, const __half* __restrict__ W,
         const float* __restrict__ b0, const float* __restrict__ b1,
         const float* __restrict__ b2, const float* __restrict__ res,
         void* __restrict__ Cv, int M, int N, int K) {
    extern __shared__ char smem[];
    __half* smem_h = (__half*)smem;
    float*  sbias  = (float*)(smem + NSTAGE * STAGE_H * 2);

    const int tid  = threadIdx.x;
    const int wid  = tid >> 5, lane = tid & 31;
    const int wm   = wid >> 1, wn = wid & 1;        // 2 x 2 warp grid, 64x64 tiles
    const int bm   = blockIdx.y * 128, bn = blockIdx.x * 128;
    const int NC   = K >> 5;

    const float* bsel = b0;
    int bcol = bn;
    if (EPI == 3) {
        const int which = bn >> 10;
        bsel = (which == 0) ? b0 : (which == 1) ? b1 : b2;
        bcol = bn & 1023;
    }
    sbias[tid] = bsel[bcol + tid];

    float acc[4][8][4];
    #pragma unroll
    for (int mt = 0; mt < 4; mt++)
        #pragma unroll
        for (int nt = 0; nt < 8; nt++)
            #pragma unroll
            for (int e = 0; e < 4; e++) acc[mt][nt][e] = 0.0f;

    load_chunk_h(smem_h, A, W, bm, bn, K, 0, tid);
    load_chunk_h(smem_h, A, W, bm, bn, K, 1, tid);
    load_chunk_h(smem_h, A, W, bm, bn, K, 2, tid);

    const int g = lane >> 3, r8 = lane & 7;
    const uint32_t sb = smem_u32(smem_h);
    const uint32_t aBase = sb + ((wm * 64 + (g & 1) * 8 + r8) * 40 + (g >> 1) * 8) * 2;
    const uint32_t bBase = sb + (STG_H + (wn * 64 + (g >> 1) * 8 + r8) * 40 + (g & 1) * 8) * 2;

    for (int c = 0; c < NC; c++) {
        const int rem = NC - 1 - c;
        if (rem >= 2)      asm volatile("cp.async.wait_group 2;" ::: "memory");
        else if (rem == 1) asm volatile("cp.async.wait_group 1;" ::: "memory");
        else               asm volatile("cp.async.wait_group 0;" ::: "memory");
        __syncthreads();

        if (c + 3 < NC) load_chunk_h(smem_h, A, W, bm, bn, K, c + 3, tid);

        const uint32_t stOff = (uint32_t)(c & (NSTAGE - 1)) * (STAGE_H * 2);
        #pragma unroll
        for (int ks = 0; ks < 2; ks++) {
            uint32_t a[4][4], b[4][4];
            #pragma unroll
            for (int mt = 0; mt < 4; mt++)
                ldsm_x4(a[mt], aBase + stOff + mt * (16 * 40 * 2) + ks * 32);
            #pragma unroll
            for (int j = 0; j < 4; j++)
                ldsm_x4(b[j], bBase + stOff + j * (16 * 40 * 2) + ks * 32);
            #pragma unroll
            for (int mt = 0; mt < 4; mt++)
                #pragma unroll
                for (int j = 0; j < 4; j++) {
                    mma_f16(acc[mt][2 * j],     a[mt], b[j]);
                    mma_f16(acc[mt][2 * j + 1], a[mt], b[j] + 2);
                }
        }
    }

    const int lr4 = lane >> 2, lc = lane & 3;
    const int cstride = (EPI == 3) ? 1024 : N;
    __half* Ch = (__half*)Cv;
    if (EPI == 3) Ch += (size_t)(bn >> 10) * M_TOK * 1024;
    const int cbn = (EPI == 3) ? (bn & 1023) : bn;

    #pragma unroll
    for (int mt = 0; mt < 4; mt++) {
        const int row0 = bm + wm * 64 + mt * 16 + lr4;
        #pragma unroll
        for (int nt = 0; nt < 8; nt++) {
            const int coll = wn * 64 + nt * 8 + lc * 2;
            const int col  = cbn + coll;
            #pragma unroll
            for (int half_i = 0; half_i < 2; half_i++) {
                const int row = row0 + half_i * 8;
                float ox = acc[mt][nt][half_i * 2 + 0] + sbias[coll];
                float oy = acc[mt][nt][half_i * 2 + 1] + sbias[coll + 1];
                if (EPI == 0 || EPI == 3) {
                    *(half2*)(Ch + (size_t)row * cstride + col) = __floats2half2_rn(ox, oy);
                } else if (EPI == 1) {
                    ox = 0.5f * ox * (1.0f + erff(ox * 0.70710678118654752f));
                    oy = 0.5f * oy * (1.0f + erff(oy * 0.70710678118654752f));
                    *(half2*)(Ch + (size_t)row * cstride + col) = __floats2half2_rn(ox, oy);
                } else {
                    const float2 rv = *(const float2*)(res + (size_t)row * N + col);
                    float2 o; o.x = ox + rv.x; o.y = oy + rv.y;
                    *(float2*)((float*)Cv + (size_t)row * N + col) = o;
                }
            }
        }
    }
}

// ---------------- Tensor-core causal flash attention (fp16, FA2-style) --------
// exp2-domain softmax with ex2.approx.f16x2: EX2 output IS the fp16 P fragment.
#define ATS 72
#define AT_TILE (64*ATS)
#define AT_SMEM ((128*ATS + 4*AT_TILE)*2)

__device__ __forceinline__ void at_prefetch(
    __half* Ks, __half* Vs, const __half* __restrict__ K, const __half* __restrict__ V,
    size_t kbase, int st, int tid) {
    __half* kd = Ks + st * AT_TILE;
    __half* vd = Vs + st * AT_TILE;
    #pragma unroll
    for (int it = 0; it < 2; it++) {
        const int i = tid + it * 256;      // 0..511
        const int row = i >> 3, seg = i & 7;
        const size_t go = kbase + (size_t)row * D_MODEL + seg * 8;
        asm volatile("cp.async.cg.shared.global [%0], [%1], 16;"
                     :: "r"(smem_u32(kd + row * ATS + seg * 8)), "l"(K + go));
        asm volatile("cp.async.cg.shared.global [%0], [%1], 16;"
                     :: "r"(smem_u32(vd + row * ATS + seg * 8)), "l"(V + go));
    }
    asm volatile("cp.async.commit_group;" ::: "memory");
}

__global__ void __launch_bounds__(256, 2)
attn_tc(const __half* __restrict__ Q, const __half* __restrict__ K,
        const __half* __restrict__ V, __half* __restrict__ O) {
    extern __shared__ __half smh[];
    __half* Qs = smh;                      // [128][72]
    __half* Ks = Qs + 128 * ATS;           // 2 x [64][72]
    __half* Vs = Ks + 2 * AT_TILE;         // 2 x [64][72] (raw [tok][d])
    const int tid = threadIdx.x;
    const int wid = tid >> 5, lane = tid & 31;
    const int g = lane >> 3, r8 = lane & 7;
    const int lr4 = lane >> 2, lc = lane & 3;

    const int qb = (gridDim.x - 1) - blockIdx.x;   // heavy tiles first
    const int h = blockIdx.y, b = blockIdx.z;
    const size_t qbase = ((size_t)(b * SEQ + qb * 128) * D_MODEL) + h * HEAD_DIM;
    const size_t kvbase0 = ((size_t)(b * SEQ) * D_MODEL) + h * HEAD_DIM;

    at_prefetch(Ks, Vs, K, V, kvbase0, 0, tid);

    // Q scale folds softmax 1/sqrt(dh) AND log2(e): 0.125 * 1.4426950408889634
    const half2 scl = __half2half2(__float2half(0.18033687919464111f));
    #pragma unroll
    for (int it = 0; it < 4; it++) {
        const int i = tid + it * 256;
        const int row = i >> 3, seg = i & 7;
        const half2* src = (const half2*)(Q + qbase + (size_t)row * D_MODEL + seg * 8);
        half2* dst = (half2*)(Qs + row * ATS + seg * 8);
        #pragma unroll
        for (int j = 0; j < 4; j++) dst[j] = __hmul2(src[j], scl);
    }

    float m[2], l[2], acc[8][4];
    m[0] = m[1] = -1e30f; l[0] = l[1] = 0.0f;
    #pragma unroll
    for (int nt = 0; nt < 8; nt++)
        #pragma unroll
        for (int e = 0; e < 4; e++) acc[nt][e] = 0.0f;

    const uint32_t qA = smem_u32(Qs) + ((wid * 16 + (g & 1) * 8 + r8) * ATS + (g >> 1) * 8) * 2;
    const uint32_t kB0 = smem_u32(Ks) + (((g >> 1) * 8 + r8) * ATS + (g & 1) * 8) * 2;
    const uint32_t vB0 = smem_u32(Vs) + (((g & 1) * 8 + r8) * ATS + (g >> 1) * 8) * 2;

    const int ntk = 2 * qb + 2;
    for (int kt = 0; kt < ntk; kt++) {
        if (kt + 1 < ntk)
            at_prefetch(Ks, Vs, K, V, kvbase0 + (size_t)(kt + 1) * 64 * D_MODEL, (kt + 1) & 1, tid);
        if (kt + 1 < ntk) asm volatile("cp.async.wait_group 1;" ::: "memory");
        else              asm volatile("cp.async.wait_group 0;" ::: "memory");
        __syncthreads();

        const uint32_t stB = (uint32_t)(kt & 1) * (AT_TILE * 2);
        const uint32_t kB = kB0 + stB, vB = vB0 + stB;

        // ---- S = Q @ K^T ----
        float s[8][4];
        #pragma unroll
        for (int nt = 0; nt < 8; nt++)
            #pragma unroll
            for (int e = 0; e < 4; e++) s[nt][e] = 0.0f;

        #pragma unroll
        for (int ks = 0; ks < 4; ks++) {
            uint32_t aQ[4];
            ldsm_x4(aQ, qA + ks * 32);
            #pragma unroll
            for (int j = 0; j < 4; j++) {
                uint32_t bb[4];
                ldsm_x4(bb, kB + j * (16 * ATS * 2) + ks * 32);
                mma_f16(s[2 * j],     aQ, bb);
                mma_f16(s[2 * j + 1], aQ, bb + 2);
            }
        }

        if (kt >= 2 * qb) {
            const int row0 = qb * 128 + wid * 16 + lr4;
            #pragma unroll
            for (int nt = 0; nt < 8; nt++) {
                const int col0 = kt * 64 + nt * 8 + 2 * lc;
                if (col0     > row0)     s[nt][0] = -1e9f;
                if (col0 + 1 > row0)     s[nt][1] = -1e9f;
                if (col0     > row0 + 8) s[nt][2] = -1e9f;
                if (col0 + 1 > row0 + 8) s[nt][3] = -1e9f;
            }
        }

        // ---- online softmax; P computed directly in fp16 via ex2.f16x2 ----
        uint32_t pp[8][2];
        #pragma unroll
        for (int hf = 0; hf < 2; hf++) {
            float mx = m[hf];
            #pragma unroll
            for (int nt = 0; nt < 8; nt++)
                mx = fmaxf(mx, fmaxf(s[nt][hf * 2], s[nt][hf * 2 + 1]));
            mx = fmaxf(mx, __shfl_xor_sync(0xFFFFFFFFu, mx, 1));
            mx = fmaxf(mx, __shfl_xor_sync(0xFFFFFFFFu, mx, 2));
            const float corr = exp2f(m[hf] - mx);
            m[hf] = mx;
            float sum = 0.0f;
            #pragma unroll
            for (int nt = 0; nt < 8; nt++) {
                const uint32_t pe = h2exp2(packh2(s[nt][hf * 2] - mx,
                                                  s[nt][hf * 2 + 1] - mx));
                pp[nt][hf] = pe;
                const float2 pf = __half22float2(*(const half2*)&pe);
                sum += pf.x + pf.y;
            }
            sum += __shfl_xor_sync(0xFFFFFFFFu, sum, 1);
            sum += __shfl_xor_sync(0xFFFFFFFFu, sum, 2);
            l[hf] = l[hf] * corr + sum;
            #pragma unroll
            for (int nt = 0; nt < 8; nt++) {
                acc[nt][hf * 2]     *= corr;
                acc[nt][hf * 2 + 1] *= corr;
            }
        }

        // ---- O += P @ V  (pp IS the A-fragment; V via ldmatrix.trans) ----
        #pragma unroll
        for (int ks = 0; ks < 4; ks++) {
            uint32_t aP[4];
            aP[0] = pp[2 * ks][0];
            aP[1] = pp[2 * ks][1];
            aP[2] = pp[2 * ks + 1][0];
            aP[3] = pp[2 * ks + 1][1];
            #pragma unroll
            for (int j = 0; j < 4; j++) {
                uint32_t bb[4];
                ldsm_x4_t(bb, vB + ks * (16 * ATS * 2) + j * 32);
                mma_f16(acc[2 * j],     aP, bb);
                mma_f16(acc[2 * j + 1], aP, bb + 2);
            }
        }
        __syncthreads();
    }

    const float inv0 = 1.0f / l[0], inv1 = 1.0f / l[1];
    const int row0 = qb * 128 + wid * 16 + lr4;
    #pragma unroll
    for (int nt = 0; nt < 8; nt++) {
        const int col = h * HEAD_DIM + nt * 8 + 2 * lc;
        *(half2*)(O + (size_t)(b * SEQ + row0) * D_MODEL + col) =
            __floats2half2_rn(acc[nt][0] * inv0, acc[nt][1] * inv0);
        *(half2*)(O + (size_t)(b * SEQ + row0 + 8) * D_MODEL + col) =
            __floats2half2_rn(acc[nt][2] * inv1, acc[nt][3] * inv1);
    }
}

// ---------------- launch ------------------------------------------------------
extern "C" void kernel_launch(void* const* d_in, const int* in_sizes, int n_in,
                              void* d_out, int out_size) {
    const float* x     = (const float*)d_in[0];
    const float* wq_w  = (const float*)d_in[2];
    const float* wq_b  = (const float*)d_in[3];
    const float* wk_w  = (const float*)d_in[4];
    const float* wk_b  = (const float*)d_in[5];
    const float* wv_w  = (const float*)d_in[6];
    const float* wv_b  = (const float*)d_in[7];
    const float* wo_w  = (const float*)d_in[8];
    const float* wo_b  = (const float*)d_in[9];
    const float* fc1_w = (const float*)d_in[10];
    const float* fc1_b = (const float*)d_in[11];
    const float* fc2_w = (const float*)d_in[12];
    const float* fc2_b = (const float*)d_in[13];
    const float* ln1_g = (const float*)d_in[14];
    const float* ln1_b = (const float*)d_in[15];
    const float* ln2_g = (const float*)d_in[16];
    const float* ln2_b = (const float*)d_in[17];

    __half *h1, *qkv, *ctx, *h2, *ff, *wh;
    float *x1;
    cudaGetSymbolAddress((void**)&h1,  g_h1);
    cudaGetSymbolAddress((void**)&qkv, g_qkv);
    cudaGetSymbolAddress((void**)&ctx, g_ctx);
    cudaGetSymbolAddress((void**)&h2,  g_h2);
    cudaGetSymbolAddress((void**)&ff,  g_ff);
    cudaGetSymbolAddress((void**)&x1,  g_x1);
    cudaGetSymbolAddress((void**)&wh,  g_wh);

    cudaFuncSetAttribute(mma_gemm<1>, cudaFuncAttributeMaxDynamicSharedMemorySize, GEMM_SMEM_BYTES);
    cudaFuncSetAttribute(mma_gemm<2>, cudaFuncAttributeMaxDynamicSharedMemorySize, GEMM_SMEM_BYTES);
    cudaFuncSetAttribute(mma_gemm<3>, cudaFuncAttributeMaxDynamicSharedMemorySize, GEMM_SMEM_BYTES);
    cudaFuncSetAttribute(attn_tc,     cudaFuncAttributeMaxDynamicSharedMemorySize, AT_SMEM);

    const int MM = 1024 * 1024;
    __half* wh_qkv = wh;
    __half* wh_o   = wh + 3 * MM;
    __half* wh_fc1 = wh + 4 * MM;
    __half* wh_fc2 = wh + 8 * MM;

    tohalf_all<<<12 * MM / 4 / 256, 256>>>(wq_w, wk_w, wv_w, wo_w, fc1_w, fc2_w, wh);

    __half* q = qkv;
    __half* k = qkv + (size_t)M_TOK * D_MODEL;
    __half* v = qkv + 2 * (size_t)M_TOK * D_MODEL;

    // --- attention sub-block (pre-norm) ---
    ln_kernel<<<M_TOK / 8, 256>>>(x, ln1_g, ln1_b, h1);
    mma_gemm<3><<<dim3(24, 32), 128, GEMM_SMEM_BYTES>>>(
        h1, wh_qkv, wq_b, wk_b, wv_b, nullptr, qkv, M_TOK, 3 * D_MODEL, D_MODEL);
    attn_tc<<<dim3(SEQ / 128, N_HEADS, BATCH), 256, AT_SMEM>>>(q, k, v, ctx);
    mma_gemm<2><<<dim3(8, 32), 128, GEMM_SMEM_BYTES>>>(
        ctx, wh_o, wo_b, nullptr, nullptr, x, x1, M_TOK, D_MODEL, D_MODEL);

    // --- FFN sub-block (pre-norm) ---
    ln_kernel<<<M_TOK / 8, 256>>>(x1, ln2_g, ln2_b, h2);
    mma_gemm<1><<<dim3(32, 32), 128, GEMM_SMEM_BYTES>>>(
        h2, wh_fc1, fc1_b, nullptr, nullptr, nullptr, ff, M_TOK, D_FF, D_MODEL);
    mma_gemm<2><<<dim3(8, 32), 128, GEMM_SMEM_BYTES>>>(
        ff, wh_fc2, fc2_b, nullptr, nullptr, x1, d_out, M_TOK, D_MODEL, D_FF);
}